// round 2
// baseline (speedup 1.0000x reference)
#include <cuda_runtime.h>
#include <math.h>
#include <stdint.h>

#define NTOK   20
#define DVEC   256
#define KSAMP  4096
#define NSTEP  19
#define OPS_N  (NSTEP*KSAMP)        /* 77824   */
#define GUM_N  (NSTEP*KSAMP*NTOK)   /* 1556480 */

__device__ float          g_S[NTOK*6];      // [i][0..2]=x_i.Wf+b, [i][3..5]=x_i.Wa
__device__ unsigned char  g_ops[OPS_N];
__device__ __align__(16) float g_gum[GUM_N];
__device__ float          g_score[KSAMP];
__device__ unsigned char  g_legal[KSAMP];

// ---------------- Threefry-2x32 (20 rounds), identical to JAX ----------------
__host__ __device__ __forceinline__ void tf_block(uint32_t k0, uint32_t k1,
                                                  uint32_t x0, uint32_t x1,
                                                  uint32_t* o0, uint32_t* o1) {
  uint32_t ks2 = k0 ^ k1 ^ 0x1BD11BDAu;
  x0 += k0; x1 += k1;
#define TF_ROT(r) { x0 += x1; x1 = (x1 << (r)) | (x1 >> (32 - (r))); x1 ^= x0; }
  TF_ROT(13) TF_ROT(15) TF_ROT(26) TF_ROT(6)
  x0 += k1;  x1 += ks2 + 1u;
  TF_ROT(17) TF_ROT(29) TF_ROT(16) TF_ROT(24)
  x0 += ks2; x1 += k0 + 2u;
  TF_ROT(13) TF_ROT(15) TF_ROT(26) TF_ROT(6)
  x0 += k0;  x1 += k1 + 3u;
  TF_ROT(17) TF_ROT(29) TF_ROT(16) TF_ROT(24)
  x0 += k1;  x1 += ks2 + 4u;
  TF_ROT(13) TF_ROT(15) TF_ROT(26) TF_ROT(6)
  x0 += ks2; x1 += k0 + 5u;
#undef TF_ROT
  *o0 = x0; *o1 = x1;
}

// partitionable random_bits (32-bit): counts = 64-bit iota -> (hi=0, lo=i),
// output = out0 ^ out1
__device__ __forceinline__ uint32_t tf_bits32(uint32_t k0, uint32_t k1, uint32_t i) {
  uint32_t a, b;
  tf_block(k0, k1, 0u, i, &a, &b);
  return a ^ b;
}

// ---------------- Kernel A: x = softmax(emb[id])*lv[id] + fixed[id]; S tables -
__global__ void prep_kernel(const int* __restrict__ ids,
                            const float* __restrict__ emb,
                            const float* __restrict__ lv,
                            const float* __restrict__ fx,
                            const float* __restrict__ Wf,
                            const float* __restrict__ Wa,
                            const float* __restrict__ bop) {
  __shared__ float red[256];
  int i = blockIdx.x, d = threadIdx.x;
  int id = ids[i];
  float e = emb[(size_t)id * DVEC + d];

  red[d] = e; __syncthreads();
  for (int s = 128; s > 0; s >>= 1) {
    if (d < s) red[d] = fmaxf(red[d], red[d + s]);
    __syncthreads();
  }
  float m = red[0]; __syncthreads();

  float ex = expf(e - m);
  red[d] = ex; __syncthreads();
  for (int s = 128; s > 0; s >>= 1) {
    if (d < s) red[d] += red[d + s];
    __syncthreads();
  }
  float ssum = red[0]; __syncthreads();

  float x = (ex / ssum) * lv[id] + fx[(size_t)id * DVEC + d];

  for (int o = 0; o < 3; o++) {
    red[d] = x * Wf[d * 3 + o]; __syncthreads();
    for (int s = 128; s > 0; s >>= 1) { if (d < s) red[d] += red[d + s]; __syncthreads(); }
    if (d == 0) g_S[i * 6 + o] = red[0] + bop[o];
    __syncthreads();
    red[d] = x * Wa[d * 3 + o]; __syncthreads();
    for (int s = 128; s > 0; s >>= 1) { if (d < s) red[d] += red[d + s]; __syncthreads(); }
    if (d == 0) g_S[i * 6 + 3 + o] = red[0];
    __syncthreads();
  }
}

// ---------------- Kernel B: ops = randint(kop, (19,4096), 0, 3) ---------------
__global__ void ops_kernel(uint32_t k0, uint32_t k1) {
  int i = blockIdx.x * blockDim.x + threadIdx.x;
  if (i >= OPS_N) return;
  uint32_t bits = tf_bits32(k0, k1, (uint32_t)i);
  // randint: multiplier = ((2^16 % 3)^2) % 3 = 1
  uint32_t hi = bits >> 16, lo = bits & 0xFFFFu;
  uint32_t off = (hi % 3u) + (lo % 3u);
  g_ops[i] = (unsigned char)(off % 3u);
}

// ---------------- Kernel C: gumbel(kg, (19,4096,20)) --------------------------
__global__ void gum_kernel(uint32_t k0, uint32_t k1) {
  int i = blockIdx.x * blockDim.x + threadIdx.x;
  if (i >= GUM_N) return;
  uint32_t bits = tf_bits32(k0, k1, (uint32_t)i);
  const float tiny = 1.17549435e-38f;
  float f = __uint_as_float((bits >> 9) | 0x3F800000u) - 1.0f;
  // uniform(tiny, 1): u*(1-tiny)+tiny with (1-tiny) == 1.0f, clamped below
  float u = fmaxf(tiny, f + tiny);
  g_gum[i] = -logf(-logf(u));
}

// ---------------- Kernel D: per-sample sequential tree construction -----------
__global__ void scan_kernel() {
  __shared__ float sS[NTOK * 6];
  if (threadIdx.x < NTOK * 6) sS[threadIdx.x] = g_S[threadIdx.x];
  __syncthreads();

  int k = blockIdx.x * blockDim.x + threadIdx.x;  // 0..4095

  unsigned avail = 0xFFFFFu;
  unsigned f1 = 0u, f2 = 0u;
  unsigned char ptr[NTOK];
#pragma unroll
  for (int j = 0; j < NTOK; j++) ptr[j] = (unsigned char)j;
  float score = 0.0f;
  bool legal = true;

  for (int t = 0; t < NSTEP; t++) {
    int op = (int)g_ops[t * KSAMP + k];
    const float4* gp = (const float4*)&g_gum[((size_t)(t * KSAMP + k)) * NTOK];
    float g[NTOK];
#pragma unroll
    for (int q = 0; q < 5; q++) {
      float4 v = gp[q];
      g[4 * q + 0] = v.x; g[4 * q + 1] = v.y; g[4 * q + 2] = v.z; g[4 * q + 3] = v.w;
    }
    // top-2 with jax.lax.top_k tie-breaking (lower index wins ties)
    float b1v = -3.0e38f, b2v = -3.0e38f;
    int b1 = 0, b2 = 0;
#pragma unroll
    for (int j = 0; j < NTOK; j++) {
      float v = ((avail >> j) & 1u) ? g[j] : -1000000000.0f;
      if (v > b1v)      { b2v = b1v; b2 = b1; b1v = v; b1 = j; }
      else if (v > b2v) { b2v = v;   b2 = j; }
    }
    avail &= ~(1u << b2);

    int pf = ptr[b1], pa = ptr[b2];
    score += sS[pf * 6 + op] + sS[pa * 6 + 3 + op];

    unsigned of1 = (f1 >> b1) & 1u;
    unsigned of2 = (f2 >> b1) & 1u;
    // bad = (arg1|arg2)&f1 | arg2&f2
    bool bad = ((op != 2) && of1) || ((op == 1) && of2);
    legal = legal && !bad;

    if (op == 2) {  // mod: slot b1 becomes a full copy of slot b2
      ptr[b1] = (unsigned char)pa;
      unsigned a1 = (f1 >> b2) & 1u, a2 = (f2 >> b2) & 1u;
      f1 = (f1 & ~(1u << b1)) | (a1 << b1);
      f2 = (f2 & ~(1u << b1)) | (a2 << b1);
    } else if (op == 0) {
      f1 |= 1u << b1;         // new_f1 = is_arg1 | f1
    } else {
      f2 |= 1u << b1;         // new_f2 = is_arg2 | f2
    }
  }
  g_score[k] = score;
  g_legal[k] = legal ? 1 : 0;
}

// ---------------- Kernel E: legal count + logsumexp + constants ---------------
__global__ void reduce_kernel(float* __restrict__ out) {
  __shared__ float sred[1024];
  __shared__ int   scnt[1024];
  int t = threadIdx.x;

  float m = -INFINITY; int c = 0;
  for (int k = t; k < KSAMP; k += 1024) {
    if (g_legal[k]) { m = fmaxf(m, g_score[k]); c++; }
  }
  sred[t] = m; scnt[t] = c; __syncthreads();
  for (int s = 512; s > 0; s >>= 1) {
    if (t < s) { sred[t] = fmaxf(sred[t], sred[t + s]); scnt[t] += scnt[t + s]; }
    __syncthreads();
  }
  float gm = sred[0]; int cnt = scnt[0]; __syncthreads();

  float sum = 0.0f;
  for (int k = t; k < KSAMP; k += 1024) {
    if (g_legal[k]) sum += expf(g_score[k] - gm);
  }
  sred[t] = sum; __syncthreads();
  for (int s = 512; s > 0; s >>= 1) {
    if (t < s) sred[t] += sred[t + s];
    __syncthreads();
  }

  if (t == 0) {
    float lse = gm + logf(sred[0]);
    double log_all = lgamma(21.0) + log(1767263190.0) + 19.0 * log(3.0);
    double res = log_all + (double)logf((float)cnt) - 2.0 * log(4096.0) + (double)lse;
    out[0] = (float)res;
  }
}

// ---------------- Launch ------------------------------------------------------
extern "C" void kernel_launch(void* const* d_in, const int* in_sizes, int n_in,
                              void* d_out, int out_size) {
  const int*   ids = (const int*)d_in[0];
  const float* emb = (const float*)d_in[1];
  const float* lv  = (const float*)d_in[2];
  const float* fx  = (const float*)d_in[3];
  const float* Wf  = (const float*)d_in[4];
  const float* Wa  = (const float*)d_in[5];
  const float* bop = (const float*)d_in[6];
  float* out = (float*)d_out;

  // jax.random.key(42) -> (0,42); partitionable foldlike split:
  // kop = TF(key; 0,0), kg = TF(key; 0,1)
  uint32_t kop0, kop1, kg0, kg1;
  tf_block(0u, 42u, 0u, 0u, &kop0, &kop1);
  tf_block(0u, 42u, 0u, 1u, &kg0, &kg1);

  prep_kernel<<<NTOK, 256>>>(ids, emb, lv, fx, Wf, Wa, bop);
  ops_kernel<<<(OPS_N + 255) / 256, 256>>>(kop0, kop1);
  gum_kernel<<<GUM_N / 256, 256>>>(kg0, kg1);
  scan_kernel<<<KSAMP / 256, 256>>>();
  reduce_kernel<<<1, 1024>>>(out);
}

// round 3
// speedup vs baseline: 1.2320x; 1.2320x over previous
#include <cuda_runtime.h>
#include <math.h>
#include <stdint.h>

#define NTOK   20
#define DVEC   256
#define KSAMP  4096
#define NSTEP  19

__device__ float          g_S[NTOK*6];   // [i][0..2]=x_i.Wf+b, [i][3..5]=x_i.Wa
__device__ float          g_score[KSAMP];
__device__ unsigned char  g_legal[KSAMP];

// ---------------- Threefry-2x32 (20 rounds), identical to JAX ----------------
__host__ __device__ __forceinline__ void tf_block(uint32_t k0, uint32_t k1,
                                                  uint32_t x0, uint32_t x1,
                                                  uint32_t* o0, uint32_t* o1) {
  uint32_t ks2 = k0 ^ k1 ^ 0x1BD11BDAu;
  x0 += k0; x1 += k1;
#define TF_ROT(r) { x0 += x1; x1 = (x1 << (r)) | (x1 >> (32 - (r))); x1 ^= x0; }
  TF_ROT(13) TF_ROT(15) TF_ROT(26) TF_ROT(6)
  x0 += k1;  x1 += ks2 + 1u;
  TF_ROT(17) TF_ROT(29) TF_ROT(16) TF_ROT(24)
  x0 += ks2; x1 += k0 + 2u;
  TF_ROT(13) TF_ROT(15) TF_ROT(26) TF_ROT(6)
  x0 += k0;  x1 += k1 + 3u;
  TF_ROT(17) TF_ROT(29) TF_ROT(16) TF_ROT(24)
  x0 += k1;  x1 += ks2 + 4u;
  TF_ROT(13) TF_ROT(15) TF_ROT(26) TF_ROT(6)
  x0 += ks2; x1 += k0 + 5u;
#undef TF_ROT
  *o0 = x0; *o1 = x1;
}

// partitionable random_bits (32-bit): counts = 64-bit iota -> (hi=0, lo=i),
// output = out0 ^ out1
__device__ __forceinline__ uint32_t tf_bits32(uint32_t k0, uint32_t k1, uint32_t i) {
  uint32_t a, b;
  tf_block(k0, k1, 0u, i, &a, &b);
  return a ^ b;
}

// ---------------- Kernel A: x = softmax(emb[id])*lv[id] + fixed[id]; S tables -
__global__ void prep_kernel(const int* __restrict__ ids,
                            const float* __restrict__ emb,
                            const float* __restrict__ lv,
                            const float* __restrict__ fx,
                            const float* __restrict__ Wf,
                            const float* __restrict__ Wa,
                            const float* __restrict__ bop) {
  __shared__ float red[256];
  int i = blockIdx.x, d = threadIdx.x;
  int id = ids[i];
  float e = emb[(size_t)id * DVEC + d];

  red[d] = e; __syncthreads();
  for (int s = 128; s > 0; s >>= 1) {
    if (d < s) red[d] = fmaxf(red[d], red[d + s]);
    __syncthreads();
  }
  float m = red[0]; __syncthreads();

  float ex = expf(e - m);
  red[d] = ex; __syncthreads();
  for (int s = 128; s > 0; s >>= 1) {
    if (d < s) red[d] += red[d + s];
    __syncthreads();
  }
  float ssum = red[0]; __syncthreads();

  float x = (ex / ssum) * lv[id] + fx[(size_t)id * DVEC + d];

  for (int o = 0; o < 3; o++) {
    red[d] = x * Wf[d * 3 + o]; __syncthreads();
    for (int s = 128; s > 0; s >>= 1) { if (d < s) red[d] += red[d + s]; __syncthreads(); }
    if (d == 0) g_S[i * 6 + o] = red[0] + bop[o];
    __syncthreads();
    red[d] = x * Wa[d * 3 + o]; __syncthreads();
    for (int s = 128; s > 0; s >>= 1) { if (d < s) red[d] += red[d + s]; __syncthreads(); }
    if (d == 0) g_S[i * 6 + 3 + o] = red[0];
    __syncthreads();
  }
}

// ---------------- Kernel B: fused gumbel+ops+scan, one warp per sample --------
__global__ __launch_bounds__(256) void fused_scan(uint32_t kop0, uint32_t kop1,
                                                  uint32_t kg0,  uint32_t kg1) {
  __shared__ float sS[NTOK * 6];
  if (threadIdx.x < NTOK * 6) sS[threadIdx.x] = g_S[threadIdx.x];
  __syncthreads();

  const unsigned FULL = 0xFFFFFFFFu;
  int lane = threadIdx.x & 31;
  int k = (blockIdx.x * blockDim.x + threadIdx.x) >> 5;  // sample 0..4095

  // ops: lane t holds op for step t (ops_all[(t,k)] flattened t*KSAMP+k)
  uint32_t opbits = tf_bits32(kop0, kop1, (uint32_t)(lane * KSAMP + k));
  int my_op = (int)(((opbits >> 16) % 3u + (opbits & 0xFFFFu) % 3u) % 3u);

  // Precompute all 19 gumbel sort-keys for this lane's slot (bit-exact JAX
  // gumbel; monotone map float->sortable uint32 preserves ordering).
  uint32_t skey[NSTEP];
  const float tiny = 1.17549435e-38f;
#pragma unroll
  for (int t = 0; t < NSTEP; t++) {
    uint32_t idx = ((uint32_t)(t * KSAMP + k)) * (uint32_t)NTOK + (uint32_t)lane;
    uint32_t bits = tf_bits32(kg0, kg1, idx);
    float f = __uint_as_float((bits >> 9) | 0x3F800000u) - 1.0f;
    float u = fmaxf(tiny, f + tiny);        // uniform(tiny,1); (1-tiny) rounds to 1
    float v = -logf(-logf(u));              // gumbel
    uint32_t vb = __float_as_uint(v);
    // sortable: negative -> ~bits, positive -> bits|signbit (order-preserving)
    skey[t] = vb ^ (((int32_t)vb >> 31) | 0x80000000u);
  }

  unsigned avail = 0xFFFFFu;     // 20 slots
  unsigned f1 = 0u, f2 = 0u;
  int myptr = lane;              // slot `lane`'s dvec-row pointer (register!)
  float score = 0.0f;
  bool legal = true;

#pragma unroll
  for (int t = 0; t < NSTEP; t++) {
    int op = __shfl_sync(FULL, my_op, t);

    // masked key: 0 for unavailable/out-of-range lanes (gumbels all map > 0)
    uint32_t s = (lane < NTOK && ((avail >> lane) & 1u)) ? skey[t] : 0u;

    // top-1: hardware warp reduce; ffs on ballot = lowest-index tie-break
    uint32_t m1 = __reduce_max_sync(FULL, s);
    int b1 = __ffs(__ballot_sync(FULL, s == m1)) - 1;
    // top-2: exclude b1 only
    uint32_t s2 = (lane == b1) ? 0u : s;
    uint32_t m2 = __reduce_max_sync(FULL, s2);
    int b2 = __ffs(__ballot_sync(FULL, s2 == m2)) - 1;

    avail &= ~(1u << b2);

    int pf = __shfl_sync(FULL, myptr, b1);
    int pa = __shfl_sync(FULL, myptr, b2);
    score += sS[pf * 6 + op] + sS[pa * 6 + 3 + op];

    unsigned of1 = (f1 >> b1) & 1u;
    unsigned of2 = (f2 >> b1) & 1u;
    // bad = (arg1|arg2)&f1 | arg2&f2
    bool bad = ((op != 2) && of1) || ((op == 1) && of2);
    legal = legal && !bad;

    if (op == 2) {  // mod: slot b1 becomes a full copy of slot b2
      if (lane == b1) myptr = pa;
      unsigned a1 = (f1 >> b2) & 1u, a2 = (f2 >> b2) & 1u;
      f1 = (f1 & ~(1u << b1)) | (a1 << b1);
      f2 = (f2 & ~(1u << b1)) | (a2 << b1);
    } else if (op == 0) {
      f1 |= 1u << b1;          // new_f1 = is_arg1 | f1
    } else {
      f2 |= 1u << b1;          // new_f2 = is_arg2 | f2
    }
  }

  if (lane == 0) {
    g_score[k] = score;
    g_legal[k] = legal ? 1 : 0;
  }
}

// ---------------- Kernel C: legal count + logsumexp + constants ---------------
__global__ void reduce_kernel(float* __restrict__ out) {
  __shared__ float sred[1024];
  __shared__ int   scnt[1024];
  int t = threadIdx.x;

  float m = -INFINITY; int c = 0;
  for (int k = t; k < KSAMP; k += 1024) {
    if (g_legal[k]) { m = fmaxf(m, g_score[k]); c++; }
  }
  sred[t] = m; scnt[t] = c; __syncthreads();
  for (int s = 512; s > 0; s >>= 1) {
    if (t < s) { sred[t] = fmaxf(sred[t], sred[t + s]); scnt[t] += scnt[t + s]; }
    __syncthreads();
  }
  float gm = sred[0]; int cnt = scnt[0]; __syncthreads();

  float sum = 0.0f;
  for (int k = t; k < KSAMP; k += 1024) {
    if (g_legal[k]) sum += expf(g_score[k] - gm);
  }
  sred[t] = sum; __syncthreads();
  for (int s = 512; s > 0; s >>= 1) {
    if (t < s) sred[t] += sred[t + s];
    __syncthreads();
  }

  if (t == 0) {
    float lse = gm + logf(sred[0]);
    double log_all = lgamma(21.0) + log(1767263190.0) + 19.0 * log(3.0);
    double res = log_all + (double)logf((float)cnt) - 2.0 * log(4096.0) + (double)lse;
    out[0] = (float)res;
  }
}

// ---------------- Launch ------------------------------------------------------
extern "C" void kernel_launch(void* const* d_in, const int* in_sizes, int n_in,
                              void* d_out, int out_size) {
  const int*   ids = (const int*)d_in[0];
  const float* emb = (const float*)d_in[1];
  const float* lv  = (const float*)d_in[2];
  const float* fx  = (const float*)d_in[3];
  const float* Wf  = (const float*)d_in[4];
  const float* Wa  = (const float*)d_in[5];
  const float* bop = (const float*)d_in[6];
  float* out = (float*)d_out;

  // jax.random.key(42) -> (0,42); partitionable foldlike split:
  // kop = TF(key; 0,0), kg = TF(key; 0,1)
  uint32_t kop0, kop1, kg0, kg1;
  tf_block(0u, 42u, 0u, 0u, &kop0, &kop1);
  tf_block(0u, 42u, 0u, 1u, &kg0, &kg1);

  prep_kernel<<<NTOK, 256>>>(ids, emb, lv, fx, Wf, Wa, bop);
  fused_scan<<<(KSAMP * 32) / 256, 256>>>(kop0, kop1, kg0, kg1);
  reduce_kernel<<<1, 1024>>>(out);
}

// round 4
// speedup vs baseline: 1.5094x; 1.2252x over previous
#include <cuda_runtime.h>
#include <math.h>
#include <stdint.h>

#define NTOK   20
#define DVEC   256
#define KSAMP  4096
#define NSTEP  19
#define WPB    8          /* warps per block in fused_scan */
#define GPW    (NSTEP*NTOK)  /* 380 gumbels per warp/sample */

__device__ float          g_S[NTOK*6];   // [i][0..2]=x_i.Wf+b, [i][3..5]=x_i.Wa
__device__ float          g_score[KSAMP];
__device__ unsigned char  g_legal[KSAMP];

// ---------------- Threefry-2x32 (20 rounds), identical to JAX ----------------
__host__ __device__ __forceinline__ void tf_block(uint32_t k0, uint32_t k1,
                                                  uint32_t x0, uint32_t x1,
                                                  uint32_t* o0, uint32_t* o1) {
  uint32_t ks2 = k0 ^ k1 ^ 0x1BD11BDAu;
  x0 += k0; x1 += k1;
#define TF_ROT(r) { x0 += x1; x1 = (x1 << (r)) | (x1 >> (32 - (r))); x1 ^= x0; }
  TF_ROT(13) TF_ROT(15) TF_ROT(26) TF_ROT(6)
  x0 += k1;  x1 += ks2 + 1u;
  TF_ROT(17) TF_ROT(29) TF_ROT(16) TF_ROT(24)
  x0 += ks2; x1 += k0 + 2u;
  TF_ROT(13) TF_ROT(15) TF_ROT(26) TF_ROT(6)
  x0 += k0;  x1 += k1 + 3u;
  TF_ROT(17) TF_ROT(29) TF_ROT(16) TF_ROT(24)
  x0 += k1;  x1 += ks2 + 4u;
  TF_ROT(13) TF_ROT(15) TF_ROT(26) TF_ROT(6)
  x0 += ks2; x1 += k0 + 5u;
#undef TF_ROT
  *o0 = x0; *o1 = x1;
}

__device__ __forceinline__ uint32_t tf_bits32(uint32_t k0, uint32_t k1, uint32_t i) {
  uint32_t a, b;
  tf_block(k0, k1, 0u, i, &a, &b);
  return a ^ b;
}

// ---------------- Kernel A: prep via warp-shuffle reductions ------------------
__global__ void prep_kernel(const int* __restrict__ ids,
                            const float* __restrict__ emb,
                            const float* __restrict__ lv,
                            const float* __restrict__ fx,
                            const float* __restrict__ Wf,
                            const float* __restrict__ Wa,
                            const float* __restrict__ bop) {
  const unsigned FULL = 0xFFFFFFFFu;
  int i = blockIdx.x, d = threadIdx.x;
  int lane = d & 31, w = d >> 5;
  __shared__ float s8[8];
  __shared__ float sdot[8][6];

  int id = ids[i];
  float e   = emb[(size_t)id * DVEC + d];
  float fxv = fx[(size_t)id * DVEC + d];
  float lvv = lv[id];
  float wf0 = Wf[d*3+0], wf1 = Wf[d*3+1], wf2 = Wf[d*3+2];
  float wa0 = Wa[d*3+0], wa1 = Wa[d*3+1], wa2 = Wa[d*3+2];

  // block max via warp shuffle + 8-wide smem hop
  float m = e;
#pragma unroll
  for (int o = 16; o; o >>= 1) m = fmaxf(m, __shfl_xor_sync(FULL, m, o));
  if (lane == 0) s8[w] = m;
  __syncthreads();
  m = s8[0];
#pragma unroll
  for (int q = 1; q < 8; q++) m = fmaxf(m, s8[q]);

  float ex = expf(e - m);
  float sm = ex;
#pragma unroll
  for (int o = 16; o; o >>= 1) sm += __shfl_xor_sync(FULL, sm, o);
  __syncthreads();                     // protect s8 reuse
  if (lane == 0) s8[w] = sm;
  __syncthreads();
  sm = s8[0];
#pragma unroll
  for (int q = 1; q < 8; q++) sm += s8[q];

  float x = (ex / sm) * lvv + fxv;

  float p0 = x*wf0, p1 = x*wf1, p2 = x*wf2, p3 = x*wa0, p4 = x*wa1, p5 = x*wa2;
#pragma unroll
  for (int o = 16; o; o >>= 1) {
    p0 += __shfl_xor_sync(FULL, p0, o);
    p1 += __shfl_xor_sync(FULL, p1, o);
    p2 += __shfl_xor_sync(FULL, p2, o);
    p3 += __shfl_xor_sync(FULL, p3, o);
    p4 += __shfl_xor_sync(FULL, p4, o);
    p5 += __shfl_xor_sync(FULL, p5, o);
  }
  if (lane == 0) {
    sdot[w][0] = p0; sdot[w][1] = p1; sdot[w][2] = p2;
    sdot[w][3] = p3; sdot[w][4] = p4; sdot[w][5] = p5;
  }
  __syncthreads();
  if (d < 6) {
    float acc = 0.0f;
#pragma unroll
    for (int q = 0; q < 8; q++) acc += sdot[q][d];
    if (d < 3) acc += bop[d];
    g_S[i * 6 + d] = acc;
  }
}

// ---------------- Kernel B: fused gumbel+ops+scan, warp per sample ------------
// All 32 lanes cooperatively generate the warp's 380 gumbel keys into smem,
// then the 19-step scan reads them back (conflict-free).
__global__ __launch_bounds__(256) void fused_scan(uint32_t kop0, uint32_t kop1,
                                                  uint32_t kg0,  uint32_t kg1) {
  __shared__ float    sS[NTOK * 6];
  __shared__ uint32_t skey[WPB][384];   // 380 used, padded

  const unsigned FULL = 0xFFFFFFFFu;
  int tid = threadIdx.x;
  int lane = tid & 31, w = tid >> 5;
  if (tid < NTOK * 6) sS[tid] = g_S[tid];

  int k = blockIdx.x * WPB + w;         // sample 0..4095

  // ops: lane t holds op for step t (flat index t*KSAMP+k)
  uint32_t opbits = tf_bits32(kop0, kop1, (uint32_t)(lane * KSAMP + k));
  int my_op = (int)(((opbits >> 16) % 3u + (opbits & 0xFFFFu) % 3u) % 3u);

  // gumbel keys: flat l = t*20+j, global index t*81920 + k*20 + j
  const float tiny = 1.17549435e-38f;
#pragma unroll
  for (int r = 0; r < 12; r++) {
    int l = lane + 32 * r;
    if (l < GPW) {
      int t = l / 20;
      int j = l - t * 20;
      uint32_t idx = (uint32_t)t * 81920u + (uint32_t)k * 20u + (uint32_t)j;
      uint32_t bits = tf_bits32(kg0, kg1, idx);
      float f = __uint_as_float((bits >> 9) | 0x3F800000u) - 1.0f;
      float u = fmaxf(tiny, f + tiny);      // uniform(tiny,1); (1-tiny)==1.0f
      float v = -logf(-logf(u));            // gumbel (bit-exact JAX path)
      uint32_t vb = __float_as_uint(v);
      // order-preserving float->uint map; all results > 0
      skey[w][l] = vb ^ (((int32_t)vb >> 31) | 0x80000000u);
    }
  }
  __syncwarp();
  __syncthreads();                          // sS ready (and skey per-warp)

  unsigned avail = 0xFFFFFu;
  unsigned f1 = 0u, f2 = 0u;
  int myptr = lane;                         // slot`lane`'s dvec-row ptr
  float score = 0.0f;
  bool legal = true;

#pragma unroll
  for (int t = 0; t < NSTEP; t++) {
    int op = __shfl_sync(FULL, my_op, t);

    uint32_t s = (lane < NTOK && ((avail >> lane) & 1u)) ? skey[w][t * 20 + lane] : 0u;

    uint32_t m1 = __reduce_max_sync(FULL, s);
    int b1 = __ffs(__ballot_sync(FULL, s == m1)) - 1;   // lowest-index tie-break
    uint32_t s2 = (lane == b1) ? 0u : s;
    uint32_t m2 = __reduce_max_sync(FULL, s2);
    int b2 = __ffs(__ballot_sync(FULL, s2 == m2)) - 1;

    avail &= ~(1u << b2);

    int pf = __shfl_sync(FULL, myptr, b1);
    int pa = __shfl_sync(FULL, myptr, b2);
    score += sS[pf * 6 + op] + sS[pa * 6 + 3 + op];

    unsigned of1 = (f1 >> b1) & 1u;
    unsigned of2 = (f2 >> b1) & 1u;
    bool bad = ((op != 2) && of1) || ((op == 1) && of2);
    legal = legal && !bad;

    if (op == 2) {                        // mod: slot b1 := copy of slot b2
      if (lane == b1) myptr = pa;
      unsigned a1 = (f1 >> b2) & 1u, a2 = (f2 >> b2) & 1u;
      f1 = (f1 & ~(1u << b1)) | (a1 << b1);
      f2 = (f2 & ~(1u << b1)) | (a2 << b1);
    } else if (op == 0) {
      f1 |= 1u << b1;
    } else {
      f2 |= 1u << b1;
    }
  }

  if (lane == 0) {
    g_score[k] = score;
    g_legal[k] = legal ? 1 : 0;
  }
}

// ---------------- Kernel C: legal count + logsumexp + constants ---------------
__global__ void reduce_kernel(float* __restrict__ out) {
  __shared__ float sred[1024];
  __shared__ int   scnt[1024];
  int t = threadIdx.x;

  float m = -INFINITY; int c = 0;
  for (int k = t; k < KSAMP; k += 1024) {
    if (g_legal[k]) { m = fmaxf(m, g_score[k]); c++; }
  }
  sred[t] = m; scnt[t] = c; __syncthreads();
  for (int s = 512; s > 0; s >>= 1) {
    if (t < s) { sred[t] = fmaxf(sred[t], sred[t + s]); scnt[t] += scnt[t + s]; }
    __syncthreads();
  }
  float gm = sred[0]; int cnt = scnt[0]; __syncthreads();

  float sum = 0.0f;
  for (int k = t; k < KSAMP; k += 1024) {
    if (g_legal[k]) sum += expf(g_score[k] - gm);
  }
  sred[t] = sum; __syncthreads();
  for (int s = 512; s > 0; s >>= 1) {
    if (t < s) sred[t] += sred[t + s];
    __syncthreads();
  }

  if (t == 0) {
    float lse = gm + logf(sred[0]);
    double log_all = lgamma(21.0) + log(1767263190.0) + 19.0 * log(3.0);
    double res = log_all + (double)logf((float)cnt) - 2.0 * log(4096.0) + (double)lse;
    out[0] = (float)res;
  }
}

// ---------------- Launch ------------------------------------------------------
extern "C" void kernel_launch(void* const* d_in, const int* in_sizes, int n_in,
                              void* d_out, int out_size) {
  const int*   ids = (const int*)d_in[0];
  const float* emb = (const float*)d_in[1];
  const float* lv  = (const float*)d_in[2];
  const float* fx  = (const float*)d_in[3];
  const float* Wf  = (const float*)d_in[4];
  const float* Wa  = (const float*)d_in[5];
  const float* bop = (const float*)d_in[6];
  float* out = (float*)d_out;

  // jax.random.key(42) -> (0,42); partitionable foldlike split
  uint32_t kop0, kop1, kg0, kg1;
  tf_block(0u, 42u, 0u, 0u, &kop0, &kop1);
  tf_block(0u, 42u, 0u, 1u, &kg0, &kg1);

  prep_kernel<<<NTOK, 256>>>(ids, emb, lv, fx, Wf, Wa, bop);
  fused_scan<<<KSAMP / WPB, 256>>>(kop0, kop1, kg0, kg1);
  reduce_kernel<<<1, 1024>>>(out);
}

// round 5
// speedup vs baseline: 1.5385x; 1.0192x over previous
#include <cuda_runtime.h>
#include <math.h>
#include <stdint.h>

#define NTOK   20
#define DVEC   256
#define KSAMP  4096
#define NSTEP  19
#define WPB    8                 /* warps (samples) per block */
#define NBLK   (KSAMP/WPB)       /* 512 blocks */
#define GPW    (NSTEP*NTOK)      /* 380 gumbel keys per sample */

__device__ float          g_S[NTOK*6];   // [i][0..2]=x_i.Wf+b, [i][3..5]=x_i.Wa
__device__ float          g_score[KSAMP];
__device__ unsigned char  g_legal[KSAMP];
__device__ int            g_prep_done  = 0;   // reset by last block each run
__device__ int            g_blocks_done = 0;  // reset by last block each run

// ---------------- Threefry-2x32 (20 rounds), identical to JAX ----------------
__host__ __device__ __forceinline__ void tf_block(uint32_t k0, uint32_t k1,
                                                  uint32_t x0, uint32_t x1,
                                                  uint32_t* o0, uint32_t* o1) {
  uint32_t ks2 = k0 ^ k1 ^ 0x1BD11BDAu;
  x0 += k0; x1 += k1;
#define TF_ROT(r) { x0 += x1; x1 = (x1 << (r)) | (x1 >> (32 - (r))); x1 ^= x0; }
  TF_ROT(13) TF_ROT(15) TF_ROT(26) TF_ROT(6)
  x0 += k1;  x1 += ks2 + 1u;
  TF_ROT(17) TF_ROT(29) TF_ROT(16) TF_ROT(24)
  x0 += ks2; x1 += k0 + 2u;
  TF_ROT(13) TF_ROT(15) TF_ROT(26) TF_ROT(6)
  x0 += k0;  x1 += k1 + 3u;
  TF_ROT(17) TF_ROT(29) TF_ROT(16) TF_ROT(24)
  x0 += k1;  x1 += ks2 + 4u;
  TF_ROT(13) TF_ROT(15) TF_ROT(26) TF_ROT(6)
  x0 += ks2; x1 += k0 + 5u;
#undef TF_ROT
  *o0 = x0; *o1 = x1;
}

__device__ __forceinline__ uint32_t tf_bits32(uint32_t k0, uint32_t k1, uint32_t i) {
  uint32_t a, b;
  tf_block(k0, k1, 0u, i, &a, &b);
  return a ^ b;
}

// ---------------- warp-per-token prep (lane owns 8 dims, shuffle-only) --------
__device__ __forceinline__ void prep_token(int i, int lane,
                                           const int* __restrict__ ids,
                                           const float* __restrict__ emb,
                                           const float* __restrict__ lv,
                                           const float* __restrict__ fx,
                                           const float* __restrict__ Wf,
                                           const float* __restrict__ Wa,
                                           const float* __restrict__ bop) {
  const unsigned FULL = 0xFFFFFFFFu;
  int id = ids[i];
  const float4* er = (const float4*)(emb + (size_t)id * DVEC);
  const float4* fr = (const float4*)(fx  + (size_t)id * DVEC);
  float4 e0 = er[lane * 2], e1 = er[lane * 2 + 1];
  float4 f0 = fr[lane * 2], f1 = fr[lane * 2 + 1];
  float lvv = lv[id];

  float ev[8] = {e0.x, e0.y, e0.z, e0.w, e1.x, e1.y, e1.z, e1.w};
  float fv[8] = {f0.x, f0.y, f0.z, f0.w, f1.x, f1.y, f1.z, f1.w};

  float m = ev[0];
#pragma unroll
  for (int j = 1; j < 8; j++) m = fmaxf(m, ev[j]);
#pragma unroll
  for (int o = 16; o; o >>= 1) m = fmaxf(m, __shfl_xor_sync(FULL, m, o));

  float ex[8]; float sm = 0.0f;
#pragma unroll
  for (int j = 0; j < 8; j++) { ex[j] = expf(ev[j] - m); sm += ex[j]; }
#pragma unroll
  for (int o = 16; o; o >>= 1) sm += __shfl_xor_sync(FULL, sm, o);

  float x[8];
#pragma unroll
  for (int j = 0; j < 8; j++) x[j] = (ex[j] / sm) * lvv + fv[j];

  float p[6] = {0, 0, 0, 0, 0, 0};
#pragma unroll
  for (int j = 0; j < 8; j++) {
    int d = lane * 8 + j;
    p[0] += x[j] * Wf[d * 3 + 0];
    p[1] += x[j] * Wf[d * 3 + 1];
    p[2] += x[j] * Wf[d * 3 + 2];
    p[3] += x[j] * Wa[d * 3 + 0];
    p[4] += x[j] * Wa[d * 3 + 1];
    p[5] += x[j] * Wa[d * 3 + 2];
  }
#pragma unroll
  for (int o = 16; o; o >>= 1) {
#pragma unroll
    for (int q = 0; q < 6; q++) p[q] += __shfl_xor_sync(FULL, p[q], o);
  }
  if (lane == 0) {
#pragma unroll
    for (int q = 0; q < 6; q++)
      g_S[i * 6 + q] = p[q] + (q < 3 ? bop[q] : 0.0f);
    __threadfence();
    atomicAdd(&g_prep_done, 1);
  }
}

// ---------------- single fused kernel -----------------------------------------
__global__ __launch_bounds__(256) void fused_all(
    uint32_t kop0, uint32_t kop1, uint32_t kg0, uint32_t kg1,
    const int* __restrict__ ids, const float* __restrict__ emb,
    const float* __restrict__ lv, const float* __restrict__ fx,
    const float* __restrict__ Wf, const float* __restrict__ Wa,
    const float* __restrict__ bop, float* __restrict__ out) {
  __shared__ uint32_t skey[WPB][384];   // 380 used; raw (bits>>9)
  __shared__ float    sS[NTOK * 6];
  __shared__ float    sred[256];
  __shared__ int      scnt[256];

  const unsigned FULL = 0xFFFFFFFFu;
  int tid = threadIdx.x;
  int lane = tid & 31, w = tid >> 5;
  int k = blockIdx.x * WPB + w;          // sample 0..4095

  // ops: lane t holds op for step t (flat index t*KSAMP+k); lanes>=19 unused
  uint32_t opbits = tf_bits32(kop0, kop1, (uint32_t)(lane * KSAMP + k));
  int my_op = (int)(((opbits >> 16) % 3u + (opbits & 0xFFFFu) % 3u) % 3u);

  // blocks 0..19, warp 0: prep one token (overlaps other blocks' key gen)
  if (blockIdx.x < NTOK && w == 0)
    prep_token(blockIdx.x, lane, ids, emb, lv, fx, Wf, Wa, bop);

  // gumbel sort-keys: ordering of -log(-log(u)) == ordering of (bits>>9)
  // (strictly monotone map; ties identical) -> no transcendentals needed.
#pragma unroll
  for (int r = 0; r < 12; r++) {
    int l = lane + 32 * r;
    if (l < GPW) {
      int t = l / 20;
      int j = l - t * 20;
      uint32_t idx = (uint32_t)t * 81920u + (uint32_t)k * 20u + (uint32_t)j;
      skey[w][l] = tf_bits32(kg0, kg1, idx) >> 9;
    }
  }
  __syncwarp();

  // wait for the 20 prep warps, then stage sS
  if (tid == 0) {
    while (*((volatile int*)&g_prep_done) != NTOK) __nanosleep(60);
  }
  __syncthreads();
  __threadfence();                       // acquire g_S
  if (tid < NTOK * 6) sS[tid] = g_S[tid];
  __syncthreads();

  unsigned avail = 0xFFFFFu;
  unsigned f1 = 0u, f2 = 0u;
  int myptr = lane;                      // slot`lane`'s dvec-row ptr (register)
  float score = 0.0f;
  bool legal = true;

#pragma unroll
  for (int t = 0; t < NSTEP; t++) {
    int op = __shfl_sync(FULL, my_op, t);

    uint32_t s = (lane < NTOK && ((avail >> lane) & 1u))
               ? skey[w][t * 20 + lane] + 1u : 0u;

    uint32_t m1 = __reduce_max_sync(FULL, s);
    int b1 = __ffs(__ballot_sync(FULL, s == m1)) - 1;   // low-index tie-break
    uint32_t s2 = (lane == b1) ? 0u : s;
    uint32_t m2 = __reduce_max_sync(FULL, s2);
    int b2 = __ffs(__ballot_sync(FULL, s2 == m2)) - 1;

    avail &= ~(1u << b2);

    int pf = __shfl_sync(FULL, myptr, b1);
    int pa = __shfl_sync(FULL, myptr, b2);
    score += sS[pf * 6 + op] + sS[pa * 6 + 3 + op];

    unsigned of1 = (f1 >> b1) & 1u;
    unsigned of2 = (f2 >> b1) & 1u;
    bool bad = ((op != 2) && of1) || ((op == 1) && of2);
    legal = legal && !bad;

    if (op == 2) {                       // mod: slot b1 := copy of slot b2
      if (lane == b1) myptr = pa;
      unsigned a1 = (f1 >> b2) & 1u, a2 = (f2 >> b2) & 1u;
      f1 = (f1 & ~(1u << b1)) | (a1 << b1);
      f2 = (f2 & ~(1u << b1)) | (a2 << b1);
    } else if (op == 0) {
      f1 |= 1u << b1;
    } else {
      f2 |= 1u << b1;
    }
  }

  if (lane == 0) {
    g_score[k] = score;
    g_legal[k] = legal ? 1 : 0;
  }

  // last-block-done final reduction
  __threadfence();
  __syncthreads();
  __shared__ int is_last;
  if (tid == 0) is_last = (atomicAdd(&g_blocks_done, 1) == NBLK - 1) ? 1 : 0;
  __syncthreads();
  if (!is_last) return;
  __threadfence();                       // acquire everyone's scores

  float m = -INFINITY; int c = 0;
  for (int q = tid; q < KSAMP; q += 256) {
    if (g_legal[q]) { m = fmaxf(m, g_score[q]); c++; }
  }
  sred[tid] = m; scnt[tid] = c; __syncthreads();
  for (int s = 128; s > 0; s >>= 1) {
    if (tid < s) { sred[tid] = fmaxf(sred[tid], sred[tid + s]); scnt[tid] += scnt[tid + s]; }
    __syncthreads();
  }
  float gm = sred[0]; int cnt = scnt[0]; __syncthreads();

  float sum = 0.0f;
  for (int q = tid; q < KSAMP; q += 256) {
    if (g_legal[q]) sum += expf(g_score[q] - gm);
  }
  sred[tid] = sum; __syncthreads();
  for (int s = 128; s > 0; s >>= 1) {
    if (tid < s) sred[tid] += sred[tid + s];
    __syncthreads();
  }

  if (tid == 0) {
    float lse = gm + logf(sred[0]);
    double log_all = lgamma(21.0) + log(1767263190.0) + 19.0 * log(3.0);
    double res = log_all + (double)logf((float)cnt) - 2.0 * log(4096.0) + (double)lse;
    out[0] = (float)res;
    g_blocks_done = 0;                   // reset for next graph replay
    g_prep_done = 0;
  }
}

// ---------------- Launch ------------------------------------------------------
extern "C" void kernel_launch(void* const* d_in, const int* in_sizes, int n_in,
                              void* d_out, int out_size) {
  const int*   ids = (const int*)d_in[0];
  const float* emb = (const float*)d_in[1];
  const float* lv  = (const float*)d_in[2];
  const float* fx  = (const float*)d_in[3];
  const float* Wf  = (const float*)d_in[4];
  const float* Wa  = (const float*)d_in[5];
  const float* bop = (const float*)d_in[6];
  float* out = (float*)d_out;

  // jax.random.key(42) -> (0,42); partitionable foldlike split
  uint32_t kop0, kop1, kg0, kg1;
  tf_block(0u, 42u, 0u, 0u, &kop0, &kop1);
  tf_block(0u, 42u, 0u, 1u, &kg0, &kg1);

  fused_all<<<NBLK, 256>>>(kop0, kop1, kg0, kg1,
                           ids, emb, lv, fx, Wf, Wa, bop, out);
}